// round 15
// baseline (speedup 1.0000x reference)
#include <cuda_runtime.h>
#include <cstdint>

#define N_NODES 10000
#define N_EDGES 160000
#define D 512

// ---------------- scratch (device globals) ----------------
__device__ float g_agg[N_NODES * D];          // segment sum
__device__ float g_h1[N_NODES * D];           // rna(silu(cat@W1+b1))
__device__ float g_h2[N_NODES * D];           // h1@W2+b2
__device__ float g_w1r[2 * D * D];            // tf32-rounded W1 [K=1024][N=512]
__device__ float g_w2r[D * D];                // tf32-rounded W2 [K=512][N=512]

__device__ __forceinline__ unsigned tf32u(float x) {
    unsigned u;
    asm("cvt.rna.tf32.f32 %0, %1;" : "=r"(u) : "f"(x));
    return u;
}
__device__ __forceinline__ float tf32f(float x) { return __uint_as_float(tf32u(x)); }

__device__ __forceinline__ unsigned smem_u32(const void* p) {
    return (unsigned)__cvta_generic_to_shared(p);
}
__device__ __forceinline__ float silu_f(float x) {
    return x / (1.0f + __expf(-x));
}

// ---------------- kernel: zero agg ----------------
__global__ void zero_kernel(float4* __restrict__ p, int n4) {
    int i = blockIdx.x * blockDim.x + threadIdx.x;
    if (i < n4) p[i] = make_float4(0.f, 0.f, 0.f, 0.f);
}

// ---------------- kernel: copy efeat -> out, scatter-add -> agg ----------------
// dst is int32 (JAX x64 disabled downcasts jnp.int64 -> int32).
__global__ void edge_kernel(const float4* __restrict__ ef,
                            const int* __restrict__ dst,
                            float4* __restrict__ out,
                            float* __restrict__ agg) {
    long long idx = (long long)blockIdx.x * blockDim.x + threadIdx.x;
    if (idx >= (long long)N_EDGES * (D / 4)) return;
    int e = (int)(idx >> 7);      // D/4 = 128
    int j = (int)(idx & 127);
    float4 v = ef[idx];
    out[idx] = v;
    int d = dst[e];
    float* p = agg + (size_t)d * D + j * 4;
    asm volatile("red.global.add.v4.f32 [%0], {%1,%2,%3,%4};"
                 :: "l"(p), "f"(v.x), "f"(v.y), "f"(v.z), "f"(v.w) : "memory");
}

// ---------------- kernel: tf32-round weights (in layout) ----------------
__global__ void wcvt_kernel(const float4* __restrict__ w, float4* __restrict__ o, int n4) {
    int i = blockIdx.x * blockDim.x + threadIdx.x;
    if (i >= n4) return;
    float4 v = w[i];
    v.x = tf32f(v.x); v.y = tf32f(v.y); v.z = tf32f(v.z); v.w = tf32f(v.w);
    o[i] = v;
}

// ---------------- GEMM: C[M,512] = [A0|A1][M,K] @ B[K,512] (+bias) ----------------
// CTA tile 128(M) x 128(N) x 16(K); 128 threads = 4 warps in 2x2 grid,
// warp tile 64x64 -> 1.0 LDS per HMMA (was 1.5), B redundancy 2x (was 4x).
// Grid = 79 x 4 = 316 blocks; 3 CTAs/SM -> 444 slots -> single wave.
// A virtual concat along K. B pre-rounded tf32. MODE 1: A cvt + silu+round epilogue.
// MODE 2: A (=h1) already rounded, plain +bias epilogue.
#define BM 128
#define BN 128
#define BK 16
#define AST 20     // (20*r + c) % 32 distinct over r:8, c:4 -> conflict-free
#define BST 136    // (136*c + col) % 32 = (8c + col) % 32 distinct over c:4, col:8

template<int MODE>
__global__ void __launch_bounds__(128, 3) gemm_tf32(
    const float* __restrict__ A0, const float* __restrict__ A1,
    const float* __restrict__ Bw,
    const float* __restrict__ bias, float* __restrict__ C,
    int M, int K)
{
    __shared__ float As[2][BM * AST];   // 2 * 10240 B
    __shared__ float Bs[2][BK * BST];   // 2 *  8704 B
    const int tid = threadIdx.x;
    const int lane = tid & 31, wid = tid >> 5;
    const int wm = wid & 1, wn = wid >> 1;      // 2x2 warp grid, warp tile 64x64
    const int r = lane >> 2, c = lane & 3;
    const int m0 = blockIdx.x * BM, n0 = blockIdx.y * BN;

    float acc[4][8][4];
#pragma unroll
    for (int i = 0; i < 4; i++)
#pragma unroll
        for (int j = 0; j < 8; j++)
#pragma unroll
            for (int k = 0; k < 4; k++) acc[i][j][k] = 0.f;

    auto load_stage = [&](int s, int kt) {
        const float* Abase = (kt < 512) ? A0 : A1;   // uniform; BK=16 never straddles 512
        int kc = kt & 511;
#pragma unroll
        for (int i = 0; i < 4; i++) {           // A: 128 rows x 16 floats = 512 x 16B chunks
            int ch = tid + i * 128;
            int row = ch >> 2, c4 = (ch & 3) * 4;
            int gm = m0 + row;
            const float* src = Abase + (size_t)(gm < M ? gm : M - 1) * 512 + kc + c4;
            unsigned dp = smem_u32(&As[s][row * AST + c4]);
            int sz = (gm < M) ? 16 : 0;
            asm volatile("cp.async.cg.shared.global [%0], [%1], 16, %2;"
                         :: "r"(dp), "l"(src), "r"(sz));
        }
#pragma unroll
        for (int i = 0; i < 4; i++) {           // B: 16 rows x 128 floats = 512 x 16B chunks
            int ch = tid + i * 128;
            int rk = ch >> 5, c4 = (ch & 31) * 4;
            const float* src = Bw + (size_t)(kt + rk) * 512 + n0 + c4;
            unsigned dp = smem_u32(&Bs[s][rk * BST + c4]);
            asm volatile("cp.async.cg.shared.global [%0], [%1], 16;"
                         :: "r"(dp), "l"(src));
        }
    };

    load_stage(0, 0);
    asm volatile("cp.async.commit_group;");

    const int NIT = K / BK;
    for (int it = 0; it < NIT; ++it) {
        int cur = it & 1;
        if (it + 1 < NIT) load_stage(cur ^ 1, (it + 1) * BK);
        asm volatile("cp.async.commit_group;");
        asm volatile("cp.async.wait_group 1;");
        __syncthreads();
        const float* as = As[cur];
        const float* bs = Bs[cur];
#pragma unroll
        for (int kk = 0; kk < BK; kk += 8) {
            unsigned a[4][4];
#pragma unroll
            for (int mt = 0; mt < 4; mt++) {
                int row0 = wm * 64 + mt * 16 + r;
                if (MODE == 1) {   // raw fp32 input: round in-register
                    a[mt][0] = tf32u(as[row0 * AST + kk + c]);
                    a[mt][1] = tf32u(as[(row0 + 8) * AST + kk + c]);
                    a[mt][2] = tf32u(as[row0 * AST + kk + c + 4]);
                    a[mt][3] = tf32u(as[(row0 + 8) * AST + kk + c + 4]);
                } else {           // h1 pre-rounded in GEMM1 epilogue
                    a[mt][0] = __float_as_uint(as[row0 * AST + kk + c]);
                    a[mt][1] = __float_as_uint(as[(row0 + 8) * AST + kk + c]);
                    a[mt][2] = __float_as_uint(as[row0 * AST + kk + c + 4]);
                    a[mt][3] = __float_as_uint(as[(row0 + 8) * AST + kk + c + 4]);
                }
            }
#pragma unroll
            for (int nt = 0; nt < 8; nt++) {
                int col = wn * 64 + nt * 8 + r;
                unsigned b0 = __float_as_uint(bs[(kk + c) * BST + col]);
                unsigned b1 = __float_as_uint(bs[(kk + c + 4) * BST + col]);
#pragma unroll
                for (int mt = 0; mt < 4; mt++) {
                    asm volatile(
                        "mma.sync.aligned.m16n8k8.row.col.f32.tf32.tf32.f32 "
                        "{%0,%1,%2,%3}, {%4,%5,%6,%7}, {%8,%9}, {%0,%1,%2,%3};"
                        : "+f"(acc[mt][nt][0]), "+f"(acc[mt][nt][1]),
                          "+f"(acc[mt][nt][2]), "+f"(acc[mt][nt][3])
                        : "r"(a[mt][0]), "r"(a[mt][1]),
                          "r"(a[mt][2]), "r"(a[mt][3]),
                          "r"(b0), "r"(b1));
                }
            }
        }
        __syncthreads();
    }

    // epilogue: +bias; MODE 1: silu + tf32-round (so GEMM2 loads cvt-free)
#pragma unroll
    for (int mt = 0; mt < 4; mt++) {
        int gr0 = m0 + wm * 64 + mt * 16 + r;
#pragma unroll
        for (int nt = 0; nt < 8; nt++) {
            int gc = n0 + wn * 64 + nt * 8 + 2 * c;
            float bx = bias[gc], by = bias[gc + 1];
            float v0 = acc[mt][nt][0] + bx, v1 = acc[mt][nt][1] + by;
            float v2 = acc[mt][nt][2] + bx, v3 = acc[mt][nt][3] + by;
            if (MODE == 1) {
                v0 = tf32f(silu_f(v0)); v1 = tf32f(silu_f(v1));
                v2 = tf32f(silu_f(v2)); v3 = tf32f(silu_f(v3));
            }
            if (gr0 < M) {
                float2 o = make_float2(v0, v1);
                *(float2*)&C[(size_t)gr0 * 512 + gc] = o;
            }
            if (gr0 + 8 < M) {
                float2 o = make_float2(v2, v3);
                *(float2*)&C[(size_t)(gr0 + 8) * 512 + gc] = o;
            }
        }
    }
}

// ---------------- LayerNorm + residual ----------------
__global__ void ln_kernel(const float* __restrict__ h2, const float* __restrict__ nfeat,
                          const float* __restrict__ lnw, const float* __restrict__ lnb,
                          float* __restrict__ out) {
    int m = blockIdx.x;
    int t = threadIdx.x;   // 128 threads, 4 floats each
    float4 v = ((const float4*)(h2 + (size_t)m * D))[t];
    float s = v.x + v.y + v.z + v.w;
    float q = v.x * v.x + v.y * v.y + v.z * v.z + v.w * v.w;
#pragma unroll
    for (int o = 16; o > 0; o >>= 1) {
        s += __shfl_xor_sync(0xffffffffu, s, o);
        q += __shfl_xor_sync(0xffffffffu, q, o);
    }
    __shared__ float ss[4], qs[4];
    int w = t >> 5;
    if ((t & 31) == 0) { ss[w] = s; qs[w] = q; }
    __syncthreads();
    s = ss[0] + ss[1] + ss[2] + ss[3];
    q = qs[0] + qs[1] + qs[2] + qs[3];
    float mu  = s * (1.0f / D);
    float var = q * (1.0f / D) - mu * mu;
    float inv = rsqrtf(var + 1e-5f);
    float4 w4 = ((const float4*)lnw)[t];
    float4 b4 = ((const float4*)lnb)[t];
    float4 nf = ((const float4*)(nfeat + (size_t)m * D))[t];
    float4 o4;
    o4.x = (v.x - mu) * inv * w4.x + b4.x + nf.x;
    o4.y = (v.y - mu) * inv * w4.y + b4.y + nf.y;
    o4.z = (v.z - mu) * inv * w4.z + b4.z + nf.z;
    o4.w = (v.w - mu) * inv * w4.w + b4.w + nf.w;
    ((float4*)(out + (size_t)m * D))[t] = o4;
}

// ---------------- launch ----------------
extern "C" void kernel_launch(void* const* d_in, const int* in_sizes, int n_in,
                              void* d_out, int out_size) {
    const float* efeat = (const float*)d_in[0];
    const float* nfeat = (const float*)d_in[1];
    const int*   dst   = (const int*)d_in[2];      // int32 (JAX x64 disabled)
    const float* W1    = (const float*)d_in[3];
    const float* b1    = (const float*)d_in[4];
    const float* W2    = (const float*)d_in[5];
    const float* b2    = (const float*)d_in[6];
    const float* lnw   = (const float*)d_in[7];
    const float* lnb   = (const float*)d_in[8];
    float* out = (float*)d_out;

    float *agg, *h1, *h2, *w1r, *w2r;
    cudaGetSymbolAddress((void**)&agg, g_agg);
    cudaGetSymbolAddress((void**)&h1,  g_h1);
    cudaGetSymbolAddress((void**)&h2,  g_h2);
    cudaGetSymbolAddress((void**)&w1r, g_w1r);
    cudaGetSymbolAddress((void**)&w2r, g_w2r);

    // 1. zero agg
    {
        int n4 = N_NODES * D / 4;
        zero_kernel<<<(n4 + 255) / 256, 256>>>((float4*)agg, n4);
    }
    // 2+3. tf32-round weights (moved before edge so edge lands in ncu's slot #4)
    wcvt_kernel<<<(2 * D * D / 4 + 255) / 256, 256>>>((const float4*)W1, (float4*)w1r, 2 * D * D / 4);
    wcvt_kernel<<<(D * D / 4 + 255) / 256, 256>>>((const float4*)W2, (float4*)w2r, D * D / 4);
    // 4. copy efeat -> out, scatter-add -> agg   (ncu profile slot)
    {
        long long total = (long long)N_EDGES * (D / 4);
        edge_kernel<<<(int)((total + 255) / 256), 256>>>((const float4*)efeat, dst, (float4*)out, agg);
    }
    // 5. GEMM1: h1 = rna(silu([agg|nfeat] @ W1 + b1))   grid 79x4 = 316, single wave @3 CTA/SM
    gemm_tf32<1><<<dim3((N_NODES + BM - 1) / BM, 512 / BN), 128>>>(
        agg, nfeat, w1r, b1, h1, N_NODES, 2 * D);
    // 6. GEMM2: h2 = h1 @ W2 + b2
    gemm_tf32<2><<<dim3((N_NODES + BM - 1) / BM, 512 / BN), 128>>>(
        h1, h1, w2r, b2, h2, N_NODES, D);
    // 7. LayerNorm + residual
    ln_kernel<<<N_NODES, 128>>>(h2, nfeat, lnw, lnb, out + (size_t)N_EDGES * D);
}

// round 17
// speedup vs baseline: 1.0793x; 1.0793x over previous
#include <cuda_runtime.h>
#include <cstdint>

#define N_NODES 10000
#define N_EDGES 160000
#define D 512

// ---------------- scratch (device globals) ----------------
__device__ float g_agg[N_NODES * D];          // segment sum
__device__ float g_h1[N_NODES * D];           // rna(silu(cat@W1+b1))
__device__ float g_h2[N_NODES * D];           // h1@W2+b2
__device__ float g_w1r[2 * D * D];            // tf32-rounded W1 [K=1024][N=512]
__device__ float g_w2r[D * D];                // tf32-rounded W2 [K=512][N=512]

__device__ __forceinline__ unsigned tf32u(float x) {
    unsigned u;
    asm("cvt.rna.tf32.f32 %0, %1;" : "=r"(u) : "f"(x));
    return u;
}
__device__ __forceinline__ float tf32f(float x) { return __uint_as_float(tf32u(x)); }

__device__ __forceinline__ unsigned smem_u32(const void* p) {
    return (unsigned)__cvta_generic_to_shared(p);
}
__device__ __forceinline__ float silu_f(float x) {
    return x / (1.0f + __expf(-x));
}

// ---------------- kernel: zero agg ----------------
__global__ void zero_kernel(float4* __restrict__ p, int n4) {
    int i = blockIdx.x * blockDim.x + threadIdx.x;
    if (i < n4) p[i] = make_float4(0.f, 0.f, 0.f, 0.f);
}

// ---------------- kernel: copy efeat -> out, scatter-add -> agg ----------------
// dst is int32 (JAX x64 disabled downcasts jnp.int64 -> int32).
// Streaming cache hints: efeat is read-once, the copy is write-once ->
// evict-first so the L2 stays available for the scatter atomics on agg.
__global__ void edge_kernel(const float4* __restrict__ ef,
                            const int* __restrict__ dst,
                            float4* __restrict__ out,
                            float* __restrict__ agg) {
    long long idx = (long long)blockIdx.x * blockDim.x + threadIdx.x;
    if (idx >= (long long)N_EDGES * (D / 4)) return;
    int e = (int)(idx >> 7);      // D/4 = 128
    int j = (int)(idx & 127);
    float4 v = __ldcs(&ef[idx]);
    __stcs(&out[idx], v);
    int d = __ldg(&dst[e]);
    float* p = agg + (size_t)d * D + j * 4;
    asm volatile("red.global.add.v4.f32 [%0], {%1,%2,%3,%4};"
                 :: "l"(p), "f"(v.x), "f"(v.y), "f"(v.z), "f"(v.w) : "memory");
}

// ---------------- kernel: tf32-round weights (in layout) ----------------
__global__ void wcvt_kernel(const float4* __restrict__ w, float4* __restrict__ o, int n4) {
    int i = blockIdx.x * blockDim.x + threadIdx.x;
    if (i >= n4) return;
    float4 v = w[i];
    v.x = tf32f(v.x); v.y = tf32f(v.y); v.z = tf32f(v.z); v.w = tf32f(v.w);
    o[i] = v;
}

// ---------------- GEMM: C[M,512] = [A0|A1][M,K] @ B[K,512] (+bias) ----------------
// Round-14 proven shape: tile 128(M) x 64(N) x 16(K); 128 threads = 4 warps
// stacked along M, warp tile 32x64. Grid 79x8=632; 5 CTAs/SM -> 740 slots -> one wave.
// A virtual concat along K. B pre-rounded tf32.
// MODE 1: A rounded in-register, epilogue silu + tf32-round (writes h1 pre-rounded).
// MODE 2: A (=h1) already rounded -> cvt-free fragment loads, plain +bias epilogue.
#define BM 128
#define BN 64
#define BK 16
#define AST 20     // (20*r + c) % 32 distinct over r:8, c:4 -> conflict-free
#define BST 72     // (72*c + col) % 32 = (8c + col) % 32 distinct over c:4, col:8

template<int MODE>
__global__ void __launch_bounds__(128, 5) gemm_tf32(
    const float* __restrict__ A0, const float* __restrict__ A1,
    const float* __restrict__ Bw,
    const float* __restrict__ bias, float* __restrict__ C,
    int M, int K)
{
    __shared__ float As[2][BM * AST];   // 2 * 10240 B
    __shared__ float Bs[2][BK * BST];   // 2 *  4608 B
    const int tid = threadIdx.x;
    const int lane = tid & 31, wm = tid >> 5;   // 4 warps stacked along M
    const int r = lane >> 2, c = lane & 3;
    const int m0 = blockIdx.x * BM, n0 = blockIdx.y * BN;

    float acc[2][8][4];
#pragma unroll
    for (int i = 0; i < 2; i++)
#pragma unroll
        for (int j = 0; j < 8; j++)
#pragma unroll
            for (int k = 0; k < 4; k++) acc[i][j][k] = 0.f;

    auto load_stage = [&](int s, int kt) {
        const float* Abase = (kt < 512) ? A0 : A1;   // uniform; BK=16 never straddles 512
        int kc = kt & 511;
#pragma unroll
        for (int i = 0; i < 4; i++) {           // A: 128 rows x 16 floats = 512 x 16B chunks
            int ch = tid + i * 128;
            int row = ch >> 2, c4 = (ch & 3) * 4;
            int gm = m0 + row;
            const float* src = Abase + (size_t)(gm < M ? gm : M - 1) * 512 + kc + c4;
            unsigned dp = smem_u32(&As[s][row * AST + c4]);
            int sz = (gm < M) ? 16 : 0;
            asm volatile("cp.async.cg.shared.global [%0], [%1], 16, %2;"
                         :: "r"(dp), "l"(src), "r"(sz));
        }
#pragma unroll
        for (int i = 0; i < 2; i++) {           // B: 16 rows x 64 floats = 256 x 16B chunks
            int ch = tid + i * 128;
            int rk = ch >> 4, c4 = (ch & 15) * 4;
            const float* src = Bw + (size_t)(kt + rk) * 512 + n0 + c4;
            unsigned dp = smem_u32(&Bs[s][rk * BST + c4]);
            asm volatile("cp.async.cg.shared.global [%0], [%1], 16;"
                         :: "r"(dp), "l"(src));
        }
    };

    load_stage(0, 0);
    asm volatile("cp.async.commit_group;");

    const int NIT = K / BK;
    for (int it = 0; it < NIT; ++it) {
        int cur = it & 1;
        if (it + 1 < NIT) load_stage(cur ^ 1, (it + 1) * BK);
        asm volatile("cp.async.commit_group;");
        asm volatile("cp.async.wait_group 1;");
        __syncthreads();
        const float* as = As[cur];
        const float* bs = Bs[cur];
#pragma unroll
        for (int kk = 0; kk < BK; kk += 8) {
            unsigned a[2][4];
            float b[8][2];
#pragma unroll
            for (int mt = 0; mt < 2; mt++) {
                int row0 = wm * 32 + mt * 16 + r;
                if (MODE == 1) {   // raw fp32 input: round in-register
                    a[mt][0] = tf32u(as[row0 * AST + kk + c]);
                    a[mt][1] = tf32u(as[(row0 + 8) * AST + kk + c]);
                    a[mt][2] = tf32u(as[row0 * AST + kk + c + 4]);
                    a[mt][3] = tf32u(as[(row0 + 8) * AST + kk + c + 4]);
                } else {           // h1 pre-rounded in GEMM1 epilogue -> no cvt
                    a[mt][0] = __float_as_uint(as[row0 * AST + kk + c]);
                    a[mt][1] = __float_as_uint(as[(row0 + 8) * AST + kk + c]);
                    a[mt][2] = __float_as_uint(as[row0 * AST + kk + c + 4]);
                    a[mt][3] = __float_as_uint(as[(row0 + 8) * AST + kk + c + 4]);
                }
            }
#pragma unroll
            for (int nt = 0; nt < 8; nt++) {
                int col = nt * 8 + r;
                b[nt][0] = bs[(kk + c) * BST + col];       // B pre-rounded: no cvt
                b[nt][1] = bs[(kk + c + 4) * BST + col];
            }
#pragma unroll
            for (int mt = 0; mt < 2; mt++)
#pragma unroll
                for (int nt = 0; nt < 8; nt++) {
                    asm volatile(
                        "mma.sync.aligned.m16n8k8.row.col.f32.tf32.tf32.f32 "
                        "{%0,%1,%2,%3}, {%4,%5,%6,%7}, {%8,%9}, {%0,%1,%2,%3};"
                        : "+f"(acc[mt][nt][0]), "+f"(acc[mt][nt][1]),
                          "+f"(acc[mt][nt][2]), "+f"(acc[mt][nt][3])
                        : "r"(a[mt][0]), "r"(a[mt][1]),
                          "r"(a[mt][2]), "r"(a[mt][3]),
                          "r"(__float_as_uint(b[nt][0])), "r"(__float_as_uint(b[nt][1])));
                }
        }
        __syncthreads();
    }

    // epilogue: +bias; MODE 1: silu + tf32-round (GEMM2 then loads cvt-free)
#pragma unroll
    for (int mt = 0; mt < 2; mt++) {
        int gr0 = m0 + wm * 32 + mt * 16 + r;
#pragma unroll
        for (int nt = 0; nt < 8; nt++) {
            int gc = n0 + nt * 8 + 2 * c;
            float bx = bias[gc], by = bias[gc + 1];
            float v0 = acc[mt][nt][0] + bx, v1 = acc[mt][nt][1] + by;
            float v2 = acc[mt][nt][2] + bx, v3 = acc[mt][nt][3] + by;
            if (MODE == 1) {
                v0 = tf32f(silu_f(v0)); v1 = tf32f(silu_f(v1));
                v2 = tf32f(silu_f(v2)); v3 = tf32f(silu_f(v3));
            }
            if (gr0 < M) {
                float2 o = make_float2(v0, v1);
                *(float2*)&C[(size_t)gr0 * 512 + gc] = o;
            }
            if (gr0 + 8 < M) {
                float2 o = make_float2(v2, v3);
                *(float2*)&C[(size_t)(gr0 + 8) * 512 + gc] = o;
            }
        }
    }
}

// ---------------- LayerNorm + residual ----------------
__global__ void ln_kernel(const float* __restrict__ h2, const float* __restrict__ nfeat,
                          const float* __restrict__ lnw, const float* __restrict__ lnb,
                          float* __restrict__ out) {
    int m = blockIdx.x;
    int t = threadIdx.x;   // 128 threads, 4 floats each
    float4 v = ((const float4*)(h2 + (size_t)m * D))[t];
    float s = v.x + v.y + v.z + v.w;
    float q = v.x * v.x + v.y * v.y + v.z * v.z + v.w * v.w;
#pragma unroll
    for (int o = 16; o > 0; o >>= 1) {
        s += __shfl_xor_sync(0xffffffffu, s, o);
        q += __shfl_xor_sync(0xffffffffu, q, o);
    }
    __shared__ float ss[4], qs[4];
    int w = t >> 5;
    if ((t & 31) == 0) { ss[w] = s; qs[w] = q; }
    __syncthreads();
    s = ss[0] + ss[1] + ss[2] + ss[3];
    q = qs[0] + qs[1] + qs[2] + qs[3];
    float mu  = s * (1.0f / D);
    float var = q * (1.0f / D) - mu * mu;
    float inv = rsqrtf(var + 1e-5f);
    float4 w4 = ((const float4*)lnw)[t];
    float4 b4 = ((const float4*)lnb)[t];
    float4 nf = ((const float4*)(nfeat + (size_t)m * D))[t];
    float4 o4;
    o4.x = (v.x - mu) * inv * w4.x + b4.x + nf.x;
    o4.y = (v.y - mu) * inv * w4.y + b4.y + nf.y;
    o4.z = (v.z - mu) * inv * w4.z + b4.z + nf.z;
    o4.w = (v.w - mu) * inv * w4.w + b4.w + nf.w;
    ((float4*)(out + (size_t)m * D))[t] = o4;
}

// ---------------- launch ----------------
extern "C" void kernel_launch(void* const* d_in, const int* in_sizes, int n_in,
                              void* d_out, int out_size) {
    const float* efeat = (const float*)d_in[0];
    const float* nfeat = (const float*)d_in[1];
    const int*   dst   = (const int*)d_in[2];      // int32 (JAX x64 disabled)
    const float* W1    = (const float*)d_in[3];
    const float* b1    = (const float*)d_in[4];
    const float* W2    = (const float*)d_in[5];
    const float* b2    = (const float*)d_in[6];
    const float* lnw   = (const float*)d_in[7];
    const float* lnb   = (const float*)d_in[8];
    float* out = (float*)d_out;

    float *agg, *h1, *h2, *w1r, *w2r;
    cudaGetSymbolAddress((void**)&agg, g_agg);
    cudaGetSymbolAddress((void**)&h1,  g_h1);
    cudaGetSymbolAddress((void**)&h2,  g_h2);
    cudaGetSymbolAddress((void**)&w1r, g_w1r);
    cudaGetSymbolAddress((void**)&w2r, g_w2r);

    // 1. zero agg
    {
        int n4 = N_NODES * D / 4;
        zero_kernel<<<(n4 + 255) / 256, 256>>>((float4*)agg, n4);
    }
    // 2. copy efeat -> out, scatter-add -> agg
    {
        long long total = (long long)N_EDGES * (D / 4);
        edge_kernel<<<(int)((total + 255) / 256), 256>>>((const float4*)efeat, dst, (float4*)out, agg);
    }
    // 3. tf32-round W1
    wcvt_kernel<<<(2 * D * D / 4 + 255) / 256, 256>>>((const float4*)W1, (float4*)w1r, 2 * D * D / 4);
    // 4. GEMM1 (ncu profile slot #4): h1 = rna(silu([agg|nfeat] @ W1 + b1))
    gemm_tf32<1><<<dim3((N_NODES + BM - 1) / BM, 512 / BN), 128>>>(
        agg, nfeat, w1r, b1, h1, N_NODES, 2 * D);
    // 5. tf32-round W2 (only needed by GEMM2)
    wcvt_kernel<<<(D * D / 4 + 255) / 256, 256>>>((const float4*)W2, (float4*)w2r, D * D / 4);
    // 6. GEMM2: h2 = h1 @ W2 + b2
    gemm_tf32<2><<<dim3((N_NODES + BM - 1) / BM, 512 / BN), 128>>>(
        h1, h1, w2r, b2, h2, N_NODES, D);
    // 7. LayerNorm + residual
    ln_kernel<<<N_NODES, 128>>>(h2, nfeat, lnw, lnb, out + (size_t)N_EDGES * D);
}